// round 17
// baseline (speedup 1.0000x reference)
#include <cuda_runtime.h>
#include <cuda_bf16.h>
#include <cstdint>

// WaveletPreprocessing: level-1 orthonormal Haar wavedec2 + waverec2 is an
// exact identity -> pure 512 MiB HBM->HBM copy (traffic-optimal).
//
// Plateau so far: ~156.0-156.6us (~6.8 TB/s, DRAM ~85.5-85.9%) across five
// runs of the best configs:
//   R7  256T x 16 f4 (occ 31.5%):  156.1 / 156.4 / 156.6 / 156.3us
//   R8  128T x 32 f4 (occ 16.3%):  156.0us
// Both sit at ~the same (warps x depth) product. R17 probes the one
// unexplored cell with upside: SAME per-warp depth (16, the measured sweet
// spot) at HIGHER occupancy -- 128T x 16 f4, launch_bounds(128,4),
// 16384 x 32KiB one-shot blocks. Regs~72 allows up to 7 blocks/SM, nearly
// doubling SM-level outstanding loads and fine-graining the ld/st phase
// interleave across block boundaries.

constexpr int UNROLL  = 16;
constexpr int THREADS = 128;
constexpr int TILE    = THREADS * UNROLL;   // 2048 float4 = 32 KiB per block

__global__ void __launch_bounds__(THREADS, 4)
haar_identity_copy_kernel(const float4* __restrict__ src,
                          float4* __restrict__ dst,
                          long long n_vec)
{
    long long base = (long long)blockIdx.x * TILE + threadIdx.x;

    if (base + (long long)(UNROLL - 1) * THREADS < n_vec) {
        // 16 genuinely-outstanding coalesced evict-first LDG.128 per thread,
        // then 16 evict-first STG.128.
        float4 v[UNROLL];
#pragma unroll
        for (int k = 0; k < UNROLL; k++)
            v[k] = __ldcs(&src[base + (long long)k * THREADS]);
#pragma unroll
        for (int k = 0; k < UNROLL; k++)
            __stcs(&dst[base + (long long)k * THREADS], v[k]);
    } else {
        // Tail tile (never taken for n_vec = 2^25, kept for shape-safety).
#pragma unroll
        for (int k = 0; k < UNROLL; k++) {
            long long idx = base + (long long)k * THREADS;
            if (idx < n_vec) __stcs(&dst[idx], __ldcs(&src[idx]));
        }
    }
}

extern "C" void kernel_launch(void* const* d_in, const int* in_sizes, int n_in,
                              void* d_out, int out_size)
{
    const float* x = (const float*)d_in[0];
    float* out = (float*)d_out;

    long long n = (long long)in_sizes[0];   // 134,217,728 floats
    long long n_vec = n / 4;                // 33,554,432 float4 (exact)

    int blocks = (int)((n_vec + TILE - 1) / TILE);  // 16384 blocks

    haar_identity_copy_kernel<<<blocks, THREADS>>>(
        (const float4*)x, (float4*)out, n_vec);

    (void)n_in; (void)out_size;
}